// round 12
// baseline (speedup 1.0000x reference)
#include <cuda_runtime.h>
#include <cuda_bf16.h>

// Round 12 resubmission of the audited Round-7 candidate (11 consecutive broker
// timeouts; no evidence, no change). A correct ~160us kernel strictly dominates
// a ~60%-probability ~90us gamble while zero passes are banked; the tensor-core
// aggregation rewrite stays gated on the first successful profile.

#define NN  4096
#define CC  256
#define KIN 128
#define ITILE 64
#define JSPLIT 4
#define JLEN  (NN / JSPLIT)   // 1024
#define JT   16               // j-tile for double buffering

typedef unsigned long long ull;

// ----------------- device scratch (no allocations allowed) -----------------
__device__ __align__(16) float  g_buf[NN * CC];          // embedded nodes g [i][h*64+f]
__device__ __align__(16) float  h_buf[NN * CC];          // attention output [i][h*64+f]
__device__ __align__(16) float4 Lpack[NN * 4];           // (s_l, e^{s_l}, e^{0.2 s_l}, 0) per (i,h)
__device__ __align__(16) float4 Rpack[NN * 4];           // (s_r, e^{s_r}, e^{0.2 s_r}, 0) per (j,h)
__device__ __align__(16) float  num_part[JSPLIT * NN * CC];   // numerator partials per j-split
__device__ __align__(16) float  D_part[JSPLIT * NN * 4];      // denominator partials
__device__ __align__(16) float  ps1_part[256 * CC];      // per-block partials of sum_i relu(W_e1 h + b)

// ----------------- packed f32x2 / cp.async helpers -----------------
__device__ __forceinline__ ull fma2(ull a, ull b, ull c) {
    ull d;
    asm("fma.rn.f32x2 %0, %1, %2, %3;" : "=l"(d) : "l"(a), "l"(b), "l"(c));
    return d;
}
__device__ __forceinline__ ull pack2(float x, float y) {
    ull d;
    asm("mov.b64 %0, {%1, %2};" : "=l"(d)
        : "r"(__float_as_uint(x)), "r"(__float_as_uint(y)));
    return d;
}
__device__ __forceinline__ float2 unpack2(ull v) {
    unsigned lo, hi;
    asm("mov.b64 {%0, %1}, %2;" : "=r"(lo), "=r"(hi) : "l"(v));
    return make_float2(__uint_as_float(lo), __uint_as_float(hi));
}
__device__ __forceinline__ unsigned smem_u32(const void* p) {
    unsigned a;
    asm("{ .reg .u64 t; cvta.to.shared.u64 t, %1; cvt.u32.u64 %0, t; }"
        : "=r"(a) : "l"(p));
    return a;
}
__device__ __forceinline__ void cp16(unsigned dst, const void* src) {
    asm volatile("cp.async.ca.shared.global [%0], [%1], 16;" :: "r"(dst), "l"(src));
}
__device__ __forceinline__ void cp4(unsigned dst, const void* src) {
    asm volatile("cp.async.ca.shared.global [%0], [%1], 4;" :: "r"(dst), "l"(src));
}
__device__ __forceinline__ void cp_commit() {
    asm volatile("cp.async.commit_group;");
}
__device__ __forceinline__ void cp_wait1() {
    asm volatile("cp.async.wait_group 1;");
}
__device__ __forceinline__ void cp_wait0() {
    asm volatile("cp.async.wait_group 0;");
}

// ----------------- embed: g = nodes @ W_emb^T  (4096 x 256 x 128) -----------------
__global__ __launch_bounds__(256) void embed_kernel(const float* __restrict__ nodes,
                                                    const float* __restrict__ W_emb) {
    __shared__ __align__(16) float nd_s[32 * KIN];   // node tile [r][k]
    __shared__ __align__(16) float ws[16 * 257];     // W chunk transposed [kk][c]
    int t  = threadIdx.x;
    int i0 = blockIdx.x * 32;

#pragma unroll
    for (int q = 0; q < 4; q++) {
        int slot = t + q * 256;
        int r  = slot >> 5;
        int k4 = (slot & 31) * 4;
        *(float4*)&nd_s[r * KIN + k4] = *(const float4*)&nodes[(i0 + r) * KIN + k4];
    }

    float acc[32];
#pragma unroll
    for (int r = 0; r < 32; r++) acc[r] = 0.f;

#pragma unroll 1
    for (int k0 = 0; k0 < KIN; k0 += 16) {
        __syncthreads();
#pragma unroll
        for (int q = 0; q < 4; q++) {
            int slot = t + q * 256;
            int c   = slot >> 2;
            int kk4 = (slot & 3) * 4;
            float4 v = *(const float4*)&W_emb[c * KIN + k0 + kk4];
            ws[(kk4 + 0) * 257 + c] = v.x;
            ws[(kk4 + 1) * 257 + c] = v.y;
            ws[(kk4 + 2) * 257 + c] = v.z;
            ws[(kk4 + 3) * 257 + c] = v.w;
        }
        __syncthreads();
#pragma unroll
        for (int kk = 0; kk < 16; kk++) {
            float w = ws[kk * 257 + t];
#pragma unroll
            for (int r = 0; r < 32; r++)
                acc[r] += nd_s[r * KIN + k0 + kk] * w;
        }
    }
#pragma unroll
    for (int r = 0; r < 32; r++)
        g_buf[(i0 + r) * CC + t] = acc[r];
}

// ----------------- s_l / s_r + factored exp precompute -----------------
// exp(leaky_relu(sl+sr)) = (sl+sr>0) ? e^{sl} e^{sr} : e^{0.2 sl} e^{0.2 sr}
__global__ void slsr_kernel(const float* __restrict__ W_att) {
    int i = blockIdx.x;
    int t = threadIdx.x;               // 128: warp = head
    int h = t >> 5, lane = t & 31;
    float al0 = W_att[lane],      al1 = W_att[32 + lane];
    float ar0 = W_att[64 + lane], ar1 = W_att[96 + lane];
    float g0 = g_buf[i * CC + h * 64 + lane];
    float g1 = g_buf[i * CC + h * 64 + 32 + lane];
    float sl = g0 * al0 + g1 * al1;
    float sr = g0 * ar0 + g1 * ar1;
#pragma unroll
    for (int o = 16; o > 0; o >>= 1) {
        sl += __shfl_down_sync(0xffffffffu, sl, o);
        sr += __shfl_down_sync(0xffffffffu, sr, o);
    }
    if (lane == 0) {
        Lpack[i * 4 + h] = make_float4(sl, __expf(sl), __expf(0.2f * sl), 0.f);
        Rpack[i * 4 + h] = make_float4(sr, __expf(sr), __expf(0.2f * sr), 0.f);
    }
}

// ----------------- aggregation partials (the 4.3G-MAC stage) -----------------
// Grid (64, 4) = 256 blocks x 256 threads, 2 CTAs/SM guaranteed -> SINGLE wave.
// Block: 64 i-rows x 1024 j-range, double-buffered cp.async staging of 16-j tiles.
// Warp w: head h = w&3, i = (w>>2)*32 + lane. Thread owns all 64 f of its head
// (32 f32x2 accumulators).
__global__ __launch_bounds__(256, 2) void agg_kernel(const int* __restrict__ adj) {
    __shared__ __align__(16) float  gs[2][JT * CC];      // 2 x 16KB
    __shared__ __align__(16) float4 rp_s[2][JT * 4];     // 2 x 1KB
    __shared__ int adj_s[2][JT * 65];                    // [jl][il] pitch 65, 2 x 4.2KB

    int t     = threadIdx.x;
    int warp  = t >> 5;
    int lane  = t & 31;
    int h     = warp & 3;
    int i_loc = ((warp >> 2) << 5) + lane;               // 0..63
    int gi0   = blockIdx.x * ITILE;
    int i     = gi0 + i_loc;
    int base  = h * 64;
    int jbeg  = blockIdx.y * JLEN;

    float4 L = Lpack[i * 4 + h];   // (sl, e^sl, e^{.2 sl})
    ull acc2[32];
#pragma unroll
    for (int p = 0; p < 32; p++) acc2[p] = 0ULL;
    float D = 0.f;

    // ---- stage issue (cp.async) for tile at j0 into buffer b ----
    auto issue_tile = [&](int j0, int b) {
        // g tile: 16 rows x 256 floats = 1024 x 16B
#pragma unroll
        for (int q = 0; q < 4; q++) {
            int slot = t + q * 256;
            int jl = slot >> 6;
            int c4 = (slot & 63) * 4;
            cp16(smem_u32(&gs[b][jl * CC + c4]),
                 &g_buf[(j0 + jl) * CC + c4]);
        }
        // adj tile: 64 il x 16 jl ints, 4B each
#pragma unroll
        for (int q = 0; q < 4; q++) {
            int slot = t + q * 256;
            int il = slot >> 4;          // 0..63
            int jl = slot & 15;
            cp4(smem_u32(&adj_s[b][jl * 65 + il]),
                &adj[(gi0 + il) * NN + j0 + jl]);
        }
        // R factors: 16 j x 4 h float4
        if (t < 64)
            cp16(smem_u32(&rp_s[b][t]),
                 &Rpack[(j0 + (t >> 2)) * 4 + (t & 3)]);
    };

    auto compute_tile = [&](int buf) {
#pragma unroll 2
        for (int jj = 0; jj < JT; jj++) {
            int    av = adj_s[buf][jj * 65 + i_loc];      // lane-consecutive, conflict-free
            float4 R  = rp_s[buf][jj * 4 + h];            // warp-uniform broadcast
            float  ts = L.x + R.x;
            float  w  = (ts > 0.f) ? L.y * R.y : L.z * R.z;
            if (av == 0) w = 0.f;
            D += w;
            ull w2 = pack2(w, w);
            const ulonglong2* grow = (const ulonglong2*)&gs[buf][jj * CC + base];
#pragma unroll
            for (int p = 0; p < 16; p++) {
                ulonglong2 gv = grow[p];
                acc2[2 * p + 0] = fma2(w2, gv.x, acc2[2 * p + 0]);
                acc2[2 * p + 1] = fma2(w2, gv.y, acc2[2 * p + 1]);
            }
        }
    };

    const int tiles = JLEN / JT;     // 64
    issue_tile(jbeg, 0);
    cp_commit();

    // steady state: branch-free loop body
#pragma unroll 1
    for (int k = 0; k < tiles - 1; k++) {
        int buf = k & 1;
        issue_tile(jbeg + (k + 1) * JT, buf ^ 1);
        cp_commit();
        cp_wait1();
        __syncthreads();
        compute_tile(buf);
        __syncthreads();   // guards re-issue into this buffer at k+2
    }
    // epilogue tile
    cp_wait0();
    __syncthreads();
    compute_tile((tiles - 1) & 1);

    int split = blockIdx.y;
#pragma unroll
    for (int p = 0; p < 16; p++) {
        float2 a = unpack2(acc2[2 * p]);
        float2 b = unpack2(acc2[2 * p + 1]);
        float4 o = make_float4(a.x, a.y, b.x, b.y);
        *(float4*)&num_part[(split * NN + i) * CC + base + 4 * p] = o;
    }
    D_part[(split * NN + i) * 4 + h] = D;
}

// ----------------- combine partials -> h_buf -----------------
__global__ __launch_bounds__(256) void combine_kernel() {
    __shared__ float Dinv[4];
    int i = blockIdx.x;
    int t = threadIdx.x;
    if (t < 4) {
        float d = 0.f;
#pragma unroll
        for (int s = 0; s < JSPLIT; s++)
            d += D_part[(s * NN + i) * 4 + t];
        Dinv[t] = 1.f / d;
    }
    __syncthreads();
    float num = 0.f;
#pragma unroll
    for (int s = 0; s < JSPLIT; s++)
        num += num_part[(s * NN + i) * CC + t];
    h_buf[i * CC + t] = num * Dinv[t >> 6];
}

// ----------------- encoder layer 1 + pooled partials -----------------
// ps1_part[b][c] = sum over block-b rows of relu(h @ W_e1^T + b_e1)[.,c]
// (encoder layer 2 folds into final: pooled = (sum relu) @ W_e2^T + N*b_e2)
__global__ __launch_bounds__(256) void mlp1_kernel(const float* __restrict__ We1,
                                                   const float* __restrict__ be1) {
    __shared__ __align__(16) float hs[16 * CC];      // h tile (16 KB)
    __shared__ __align__(16) float ws[8 * 257];      // W_e1 chunk transposed
    int t  = threadIdx.x;
    int i0 = blockIdx.x * 16;

#pragma unroll
    for (int q = 0; q < 4; q++) {
        int slot = t + q * 256;
        int r  = slot >> 6;
        int c4 = (slot & 63) * 4;
        *(float4*)&hs[r * CC + c4] = *(const float4*)&h_buf[(i0 + r) * CC + c4];
    }

    float acc[16];
#pragma unroll
    for (int r = 0; r < 16; r++) acc[r] = 0.f;

#pragma unroll 1
    for (int k0 = 0; k0 < CC; k0 += 8) {
        __syncthreads();
#pragma unroll
        for (int q = 0; q < 2; q++) {
            int slot = t + q * 256;
            int c   = slot >> 1;
            int kk4 = (slot & 1) * 4;
            float4 v = *(const float4*)&We1[c * CC + k0 + kk4];
            ws[(kk4 + 0) * 257 + c] = v.x;
            ws[(kk4 + 1) * 257 + c] = v.y;
            ws[(kk4 + 2) * 257 + c] = v.z;
            ws[(kk4 + 3) * 257 + c] = v.w;
        }
        __syncthreads();
#pragma unroll
        for (int kk = 0; kk < 8; kk++) {
            float w = ws[kk * 257 + t];
#pragma unroll
            for (int r = 0; r < 16; r++)
                acc[r] += hs[r * CC + k0 + kk] * w;
        }
    }
    float bias = be1[t];
    float part = 0.f;
#pragma unroll
    for (int r = 0; r < 16; r++)
        part += fmaxf(acc[r] + bias, 0.f);
    ps1_part[blockIdx.x * CC + t] = part;   // deterministic (no atomics)
}

// ----------------- final: pooled -> decoder -> scalar out -----------------
__global__ void final_kernel(const float* __restrict__ We2, const float* __restrict__ be2,
                             const float* __restrict__ Wd1, const float* __restrict__ bd1,
                             const float* __restrict__ Wd2, const float* __restrict__ bd2,
                             float* __restrict__ out) {
    __shared__ float ps1_s[CC];
    __shared__ float pooled_s[CC];
    __shared__ float red[8];
    int t = threadIdx.x;

    float s = 0.f;
    for (int b = 0; b < 256; b++) s += ps1_part[b * CC + t];
    ps1_s[t] = s;
    __syncthreads();

    // pooled = (sum_i relu1) @ W_e2^T + N * b_e2
    float acc = 0.f;
    for (int k = 0; k < CC; k++) acc += We2[t * CC + k] * ps1_s[k];
    pooled_s[t] = acc + 4096.f * be2[t];
    __syncthreads();

    // z = relu(pooled @ W_d1^T + b_d1); out = z @ W_d2^T + b_d2
    float acc2 = 0.f;
    for (int k = 0; k < CC; k++) acc2 += Wd1[t * CC + k] * pooled_s[k];
    float z = fmaxf(acc2 + bd1[t], 0.f);
    float v = z * Wd2[t];
#pragma unroll
    for (int o = 16; o > 0; o >>= 1) v += __shfl_down_sync(0xffffffffu, v, o);
    if ((t & 31) == 0) red[t >> 5] = v;
    __syncthreads();
    if (t == 0) {
        float r = 0.f;
        for (int q = 0; q < 8; q++) r += red[q];
        out[0] = r + bd2[0];
    }
}

// ----------------- launch -----------------
extern "C" void kernel_launch(void* const* d_in, const int* in_sizes, int n_in,
                              void* d_out, int out_size) {
    const float* nodes = (const float*)d_in[0];
    const int*   adj   = (const int*)  d_in[1];
    const float* W_emb = (const float*)d_in[2];
    const float* W_att = (const float*)d_in[3];
    const float* We1   = (const float*)d_in[4];
    const float* be1   = (const float*)d_in[5];
    const float* We2   = (const float*)d_in[6];
    const float* be2   = (const float*)d_in[7];
    const float* Wd1   = (const float*)d_in[8];
    const float* bd1   = (const float*)d_in[9];
    const float* Wd2   = (const float*)d_in[10];
    const float* bd2   = (const float*)d_in[11];
    float* out = (float*)d_out;

    embed_kernel<<<128, 256>>>(nodes, W_emb);
    slsr_kernel<<<NN, 128>>>(W_att);
    agg_kernel<<<dim3(NN / ITILE, JSPLIT), 256>>>(adj);
    combine_kernel<<<NN, 256>>>();
    mlp1_kernel<<<256, 256>>>(We1, be1);
    final_kernel<<<1, 256>>>(We2, be2, Wd1, bd1, Wd2, bd2, out);
}